// round 3
// baseline (speedup 1.0000x reference)
#include <cuda_runtime.h>
#include <math.h>

#define NTOK 16384
#define KDIM 2048
#define PDIM 256
#define EDIM 64

#define BM 128
#define BN 128
#define BK 16
#define NKT (KDIM / BK)

// Scratch (static device globals; no runtime allocation)
__device__ float g_h[NTOK * PDIM];       // 16 MB: projector output
__device__ float g_Ssc[PDIM * EDIM];     // column-normalized, pre-scaled sim matrix
__device__ int   g_active;

// ---------------------------------------------------------------------------
// Kernel 0: normalize sim_matrix columns, fold in logit scale, count active
// ---------------------------------------------------------------------------
__global__ void prep_kernel(const float* __restrict__ sim,
                            const float* __restrict__ temp,
                            const float* __restrict__ mask) {
    int e = threadIdx.x;  // 64 threads, one per expert column
    __shared__ float msum[EDIM];
    float scale = expf(fminf(temp[0], 4.605170185988091f));  // log(100)
    float ss = 0.f;
    for (int p = 0; p < PDIM; ++p) {
        float v = sim[p * EDIM + e];
        ss = fmaf(v, v, ss);
    }
    float f = scale / fmaxf(sqrtf(ss), 1e-12f);
    for (int p = 0; p < PDIM; ++p)
        g_Ssc[p * EDIM + e] = sim[p * EDIM + e] * f;
    msum[e] = mask[e];
    __syncthreads();
    if (e == 0) {
        float s = 0.f;
        for (int i = 0; i < EDIM; ++i) s += msum[i];
        g_active = (int)s;
    }
}

// ---------------------------------------------------------------------------
// Kernel 1: h = x @ W^T + b   (fp32 SGEMM, 128x128x16 tiles, 8x8/thread)
// ---------------------------------------------------------------------------
__global__ __launch_bounds__(256, 2)
void gemm_kernel(const float* __restrict__ A,   // x  [NTOK, KDIM]
                 const float* __restrict__ B,   // W  [PDIM, KDIM]
                 const float* __restrict__ bias) {
    __shared__ float As[2][BK][BM + 4];
    __shared__ float Bs[2][BK][BN + 4];

    const int tid = threadIdx.x;
    const int bm = blockIdx.x * BM;
    const int bn = blockIdx.y * BN;

    // global->smem load mapping: 512 float4 per tile, 2 per thread
    const int r0 = tid >> 2;        // rows 0..63
    const int r1 = r0 + 64;         // rows 64..127
    const int kq = (tid & 3) * 4;   // k offset within BK

    const int tx = tid & 15;        // output col subtile
    const int ty = tid >> 4;        // output row subtile

    const float* Ag = A + (size_t)bm * KDIM;
    const float* Bg = B + (size_t)bn * KDIM;

    float acc[8][8];
#pragma unroll
    for (int i = 0; i < 8; ++i)
#pragma unroll
        for (int j = 0; j < 8; ++j) acc[i][j] = 0.f;

    // prologue: load tile 0
    float4 a0 = *(const float4*)(Ag + (size_t)r0 * KDIM + kq);
    float4 a1 = *(const float4*)(Ag + (size_t)r1 * KDIM + kq);
    float4 b0 = *(const float4*)(Bg + (size_t)r0 * KDIM + kq);
    float4 b1 = *(const float4*)(Bg + (size_t)r1 * KDIM + kq);

    As[0][kq + 0][r0] = a0.x; As[0][kq + 1][r0] = a0.y;
    As[0][kq + 2][r0] = a0.z; As[0][kq + 3][r0] = a0.w;
    As[0][kq + 0][r1] = a1.x; As[0][kq + 1][r1] = a1.y;
    As[0][kq + 2][r1] = a1.z; As[0][kq + 3][r1] = a1.w;
    Bs[0][kq + 0][r0] = b0.x; Bs[0][kq + 1][r0] = b0.y;
    Bs[0][kq + 2][r0] = b0.z; Bs[0][kq + 3][r0] = b0.w;
    Bs[0][kq + 0][r1] = b1.x; Bs[0][kq + 1][r1] = b1.y;
    Bs[0][kq + 2][r1] = b1.z; Bs[0][kq + 3][r1] = b1.w;
    __syncthreads();

    int buf = 0;
    for (int kt = 0; kt < NKT; ++kt) {
        float4 na0, na1, nb0, nb1;
        const bool more = (kt + 1 < NKT);
        if (more) {
            int ko = (kt + 1) * BK + kq;
            na0 = *(const float4*)(Ag + (size_t)r0 * KDIM + ko);
            na1 = *(const float4*)(Ag + (size_t)r1 * KDIM + ko);
            nb0 = *(const float4*)(Bg + (size_t)r0 * KDIM + ko);
            nb1 = *(const float4*)(Bg + (size_t)r1 * KDIM + ko);
        }
#pragma unroll
        for (int kk = 0; kk < BK; ++kk) {
            float4 av0 = *(const float4*)&As[buf][kk][ty * 8];
            float4 av1 = *(const float4*)&As[buf][kk][ty * 8 + 4];
            float4 bv0 = *(const float4*)&Bs[buf][kk][tx * 8];
            float4 bv1 = *(const float4*)&Bs[buf][kk][tx * 8 + 4];
            float ar[8] = {av0.x, av0.y, av0.z, av0.w, av1.x, av1.y, av1.z, av1.w};
            float br[8] = {bv0.x, bv0.y, bv0.z, bv0.w, bv1.x, bv1.y, bv1.z, bv1.w};
#pragma unroll
            for (int i = 0; i < 8; ++i)
#pragma unroll
                for (int j = 0; j < 8; ++j)
                    acc[i][j] = fmaf(ar[i], br[j], acc[i][j]);
        }
        if (more) {
            int nb2 = buf ^ 1;
            As[nb2][kq + 0][r0] = na0.x; As[nb2][kq + 1][r0] = na0.y;
            As[nb2][kq + 2][r0] = na0.z; As[nb2][kq + 3][r0] = na0.w;
            As[nb2][kq + 0][r1] = na1.x; As[nb2][kq + 1][r1] = na1.y;
            As[nb2][kq + 2][r1] = na1.z; As[nb2][kq + 3][r1] = na1.w;
            Bs[nb2][kq + 0][r0] = nb0.x; Bs[nb2][kq + 1][r0] = nb0.y;
            Bs[nb2][kq + 2][r0] = nb0.z; Bs[nb2][kq + 3][r0] = nb0.w;
            Bs[nb2][kq + 0][r1] = nb1.x; Bs[nb2][kq + 1][r1] = nb1.y;
            Bs[nb2][kq + 2][r1] = nb1.z; Bs[nb2][kq + 3][r1] = nb1.w;
            __syncthreads();
            buf = nb2;
        }
    }

    // epilogue: bias + store
#pragma unroll
    for (int i = 0; i < 8; ++i) {
        int m = bm + ty * 8 + i;
#pragma unroll
        for (int jj = 0; jj < 2; ++jj) {
            int p = bn + tx * 8 + jj * 4;
            float4 v;
            v.x = acc[i][jj * 4 + 0] + __ldg(&bias[p + 0]);
            v.y = acc[i][jj * 4 + 1] + __ldg(&bias[p + 1]);
            v.z = acc[i][jj * 4 + 2] + __ldg(&bias[p + 2]);
            v.w = acc[i][jj * 4 + 3] + __ldg(&bias[p + 3]);
            *(float4*)&g_h[(size_t)m * PDIM + p] = v;
        }
    }
}

// ---------------------------------------------------------------------------
// Kernel 2: per-token epilogue: row-norm, logits = (h.s)/||h||, mask,
//           softmax + threshold count -> top_k
// ---------------------------------------------------------------------------
#define TT 32
#define SS_PITCH 68
#define HS_PITCH 260
#define LS_PITCH 65
#define EPI_SMEM_FLOATS (PDIM * SS_PITCH + TT * HS_PITCH + TT * LS_PITCH + TT)
#define EPI_SMEM_BYTES (EPI_SMEM_FLOATS * 4)

__global__ __launch_bounds__(256)
void epi_kernel(const float* __restrict__ mask,
                float* __restrict__ out_logits,
                float* __restrict__ out_topk) {
    extern __shared__ float sm[];
    float* Ss = sm;                        // [PDIM][68]
    float* Hs = Ss + PDIM * SS_PITCH;      // [TT][260]
    float* Ls = Hs + TT * HS_PITCH;        // [TT][65]
    float* Rn = Ls + TT * LS_PITCH;        // [TT]

    const int tid = threadIdx.x;
    const int tok0 = blockIdx.x * TT;

    // stage Ssc (256x64)
    for (int i = tid; i < PDIM * 16; i += 256) {
        int p = i >> 4, c = (i & 15) * 4;
        float4 v = *(const float4*)&g_Ssc[p * EDIM + c];
        *(float4*)&Ss[p * SS_PITCH + c] = v;
    }
    // stage h rows (32x256)
    for (int i = tid; i < TT * 64; i += 256) {
        int t = i >> 6, c = (i & 63) * 4;
        float4 v = *(const float4*)&g_h[(size_t)(tok0 + t) * PDIM + c];
        *(float4*)&Hs[t * HS_PITCH + c] = v;
    }
    __syncthreads();

    // inverse row norms: 8 threads per row
    {
        int r = tid >> 3, sg = tid & 7;
        float ss = 0.f;
#pragma unroll
        for (int c = 0; c < 8; ++c) {
            float4 v = *(const float4*)&Hs[r * HS_PITCH + sg * 32 + c * 4];
            ss = fmaf(v.x, v.x, ss); ss = fmaf(v.y, v.y, ss);
            ss = fmaf(v.z, v.z, ss); ss = fmaf(v.w, v.w, ss);
        }
        ss += __shfl_xor_sync(0xffffffffu, ss, 1);
        ss += __shfl_xor_sync(0xffffffffu, ss, 2);
        ss += __shfl_xor_sync(0xffffffffu, ss, 4);
        if (sg == 0) Rn[r] = 1.0f / fmaxf(sqrtf(ss), 1e-12f);
    }
    __syncthreads();

    // logits: 2 tokens x 4 experts per thread
    {
        const int e0 = (tid & 15) * 4;
        const int t0 = (tid >> 4) * 2;
        float acc[2][4];
#pragma unroll
        for (int a = 0; a < 2; ++a)
#pragma unroll
            for (int j = 0; j < 4; ++j) acc[a][j] = 0.f;

        for (int p = 0; p < PDIM; p += 4) {
            float4 h0 = *(const float4*)&Hs[t0 * HS_PITCH + p];
            float4 h1 = *(const float4*)&Hs[(t0 + 1) * HS_PITCH + p];
            float4 s0 = *(const float4*)&Ss[(p + 0) * SS_PITCH + e0];
            float4 s1 = *(const float4*)&Ss[(p + 1) * SS_PITCH + e0];
            float4 s2 = *(const float4*)&Ss[(p + 2) * SS_PITCH + e0];
            float4 s3 = *(const float4*)&Ss[(p + 3) * SS_PITCH + e0];
            float sj[4][4] = {{s0.x, s0.y, s0.z, s0.w},
                              {s1.x, s1.y, s1.z, s1.w},
                              {s2.x, s2.y, s2.z, s2.w},
                              {s3.x, s3.y, s3.z, s3.w}};
            float hh0[4] = {h0.x, h0.y, h0.z, h0.w};
            float hh1[4] = {h1.x, h1.y, h1.z, h1.w};
#pragma unroll
            for (int q = 0; q < 4; ++q)
#pragma unroll
                for (int j = 0; j < 4; ++j) {
                    acc[0][j] = fmaf(hh0[q], sj[q][j], acc[0][j]);
                    acc[1][j] = fmaf(hh1[q], sj[q][j], acc[1][j]);
                }
        }

        float4 mk = *(const float4*)&mask[e0];
        float mka[4] = {mk.x, mk.y, mk.z, mk.w};
#pragma unroll
        for (int a = 0; a < 2; ++a) {
            int t = t0 + a;
            float rv = Rn[t];
            float4 v;
            float vv[4];
#pragma unroll
            for (int j = 0; j < 4; ++j) {
                float val = acc[a][j] * rv;
                if (mka[j] == 0.f) val = -1e9f;
                vv[j] = val;
                Ls[t * LS_PITCH + e0 + j] = val;
            }
            v.x = vv[0]; v.y = vv[1]; v.z = vv[2]; v.w = vv[3];
            *(float4*)&out_logits[(size_t)(tok0 + t) * EDIM + e0] = v;
        }
    }
    __syncthreads();

    // softmax + exact threshold count (1 thread / token)
    if (tid < TT) {
        const int t = tid;
        float mx = -3.402823466e38f;
        for (int e = 0; e < EDIM; ++e) mx = fmaxf(mx, Ls[t * LS_PITCH + e]);
        float s[EDIM];
        float Z = 0.f;
        for (int e = 0; e < EDIM; ++e) {
            float ex = expf(Ls[t * LS_PITCH + e] - mx);
            s[e] = ex;
            Z += ex;
        }
        float invZ = 1.0f / Z;
        for (int e = 0; e < EDIM; ++e) s[e] = s[e] * invZ + 1e-14f;

        // keep[j] (in descending-sorted order) <=> (sum of strictly-greater
        // values + tie-prefix) < THRESHOLD. Exact incl. ties, no sort needed.
        int cnt = 0;
        for (int j = 0; j < EDIM; ++j) {
            float vj = s[j];
            float G = 0.f;
            int eqb = 0;
            for (int i = 0; i < EDIM; ++i) {
                float vi = s[i];
                if (vi > vj) G += vi;
                if (vi == vj && i < j) eqb++;
            }
            if (G + (float)eqb * vj < 1.0f) cnt++;
        }
        int active = g_active;
        if (cnt > active) cnt = active;
        out_topk[tok0 + t] = (float)cnt;
    }
}

// ---------------------------------------------------------------------------
extern "C" void kernel_launch(void* const* d_in, const int* in_sizes, int n_in,
                              void* d_out, int out_size) {
    const float* x    = (const float*)d_in[0];
    const float* W    = (const float*)d_in[1];
    const float* b    = (const float*)d_in[2];
    const float* sim  = (const float*)d_in[3];
    const float* temp = (const float*)d_in[4];
    const float* mask = (const float*)d_in[5];
    float* out = (float*)d_out;

    cudaFuncSetAttribute(epi_kernel, cudaFuncAttributeMaxDynamicSharedMemorySize,
                         EPI_SMEM_BYTES);

    prep_kernel<<<1, EDIM>>>(sim, temp, mask);
    gemm_kernel<<<dim3(NTOK / BM, PDIM / BN), 256>>>(x, W, b);
    epi_kernel<<<NTOK / TT, 256, EPI_SMEM_BYTES>>>(mask, out, out + (size_t)NTOK * EDIM);
}

// round 9
// speedup vs baseline: 2.7024x; 2.7024x over previous
#include <cuda_runtime.h>
#include <cuda_bf16.h>
#include <math.h>
#include <stdint.h>

#define NTOK 16384
#define KDIM 2048
#define PDIM 256
#define EDIM 64

// ---------------- static device scratch (no runtime allocation) -------------
__device__ float g_h[NTOK * PDIM];                            // 16 MB
__device__ float g_Ssc[PDIM * EDIM];
__device__ int   g_active;
__device__ __align__(16) __nv_bfloat16 g_xhi[NTOK * KDIM];    // 64 MB
__device__ __align__(16) __nv_bfloat16 g_xlo[NTOK * KDIM];    // 64 MB
__device__ __align__(16) __nv_bfloat16 g_whi[PDIM * KDIM];    // 1 MB
__device__ __align__(16) __nv_bfloat16 g_wlo[PDIM * KDIM];    // 1 MB

// ---------------- helpers ----------------------------------------------------
__device__ __forceinline__ uint32_t smem_u32(const void* p) {
    uint32_t a;
    asm("{ .reg .u64 t; cvta.to.shared.u64 t, %1; cvt.u32.u64 %0, t; }"
        : "=r"(a) : "l"(p));
    return a;
}
__device__ __forceinline__ void cp_async16(uint32_t dst, const void* src) {
    asm volatile("cp.async.cg.shared.global [%0], [%1], 16;" :: "r"(dst), "l"(src) : "memory");
}
#define CP_COMMIT() asm volatile("cp.async.commit_group;" ::: "memory")
#define CP_WAIT1()  asm volatile("cp.async.wait_group 1;" ::: "memory")

#define LDSM4(r, addr) \
    asm volatile("ldmatrix.sync.aligned.m8n8.x4.shared.b16 {%0,%1,%2,%3}, [%4];" \
        : "=r"((r)[0]), "=r"((r)[1]), "=r"((r)[2]), "=r"((r)[3]) : "r"(addr))

#define MMA16816(d, a, b) \
    asm volatile("mma.sync.aligned.m16n8k16.row.col.f32.bf16.bf16.f32 " \
        "{%0,%1,%2,%3}, {%4,%5,%6,%7}, {%8,%9}, {%0,%1,%2,%3};" \
        : "+f"((d)[0]), "+f"((d)[1]), "+f"((d)[2]), "+f"((d)[3]) \
        : "r"((a)[0]), "r"((a)[1]), "r"((a)[2]), "r"((a)[3]), \
          "r"((b)[0]), "r"((b)[1]))

__device__ __forceinline__ uint32_t packbf(__nv_bfloat16 a, __nv_bfloat16 b) {
    __nv_bfloat162 p; p.x = a; p.y = b;
    return *reinterpret_cast<uint32_t*>(&p);
}

// ---------------- kernel 0: hi/lo bf16 splits --------------------------------
__global__ __launch_bounds__(256) void split_x_kernel(const float* __restrict__ src) {
    size_t i = ((size_t)blockIdx.x * 256 + threadIdx.x) * 8;
    float4 a = *(const float4*)(src + i);
    float4 b = *(const float4*)(src + i + 4);
    float f[8] = {a.x, a.y, a.z, a.w, b.x, b.y, b.z, b.w};
    uint32_t h[4], l[4];
#pragma unroll
    for (int j = 0; j < 4; ++j) {
        __nv_bfloat16 h0 = __float2bfloat16_rn(f[2*j]);
        __nv_bfloat16 h1 = __float2bfloat16_rn(f[2*j+1]);
        float r0 = f[2*j]   - __bfloat162float(h0);
        float r1 = f[2*j+1] - __bfloat162float(h1);
        h[j] = packbf(h0, h1);
        l[j] = packbf(__float2bfloat16_rn(r0), __float2bfloat16_rn(r1));
    }
    *(uint4*)(g_xhi + i) = make_uint4(h[0], h[1], h[2], h[3]);
    *(uint4*)(g_xlo + i) = make_uint4(l[0], l[1], l[2], l[3]);
}
__global__ __launch_bounds__(256) void split_w_kernel(const float* __restrict__ src) {
    size_t i = ((size_t)blockIdx.x * 256 + threadIdx.x) * 8;
    float4 a = *(const float4*)(src + i);
    float4 b = *(const float4*)(src + i + 4);
    float f[8] = {a.x, a.y, a.z, a.w, b.x, b.y, b.z, b.w};
    uint32_t h[4], l[4];
#pragma unroll
    for (int j = 0; j < 4; ++j) {
        __nv_bfloat16 h0 = __float2bfloat16_rn(f[2*j]);
        __nv_bfloat16 h1 = __float2bfloat16_rn(f[2*j+1]);
        float r0 = f[2*j]   - __bfloat162float(h0);
        float r1 = f[2*j+1] - __bfloat162float(h1);
        h[j] = packbf(h0, h1);
        l[j] = packbf(__float2bfloat16_rn(r0), __float2bfloat16_rn(r1));
    }
    *(uint4*)(g_whi + i) = make_uint4(h[0], h[1], h[2], h[3]);
    *(uint4*)(g_wlo + i) = make_uint4(l[0], l[1], l[2], l[3]);
}

// ---------------- kernel 1: prep Ssc (fp32) + active count -------------------
__global__ __launch_bounds__(256) void prep_kernel(const float* __restrict__ sim,
                                                   const float* __restrict__ temp,
                                                   const float* __restrict__ mask) {
    __shared__ float ssp[4][EDIM];
    __shared__ float fcol[EDIM];
    const int tid = threadIdx.x;
    const int e = tid & 63, seg = tid >> 6;
    float ss = 0.f;
    for (int p = seg * 64; p < seg * 64 + 64; ++p) {
        float v = sim[p * EDIM + e];
        ss = fmaf(v, v, ss);
    }
    ssp[seg][e] = ss;
    __syncthreads();
    if (seg == 0) {
        float tot = ssp[0][e] + ssp[1][e] + ssp[2][e] + ssp[3][e];
        float scale = expf(fminf(temp[0], 4.605170185988091f));
        fcol[e] = scale / fmaxf(sqrtf(tot), 1e-12f);
        if (e == 0) {
            float s = 0.f;
            for (int i = 0; i < EDIM; ++i) s += mask[i];
            g_active = (int)s;
        }
    }
    __syncthreads();
    float f = fcol[e];
    for (int p = seg * 64; p < seg * 64 + 64; ++p)
        g_Ssc[p * EDIM + e] = sim[p * EDIM + e] * f;
}

// ---------------- kernel 2: h = x @ W^T + b  (HMMA bf16 3-split) -------------
#define GBM 128
#define GBN 128
#define GBK 32
#define NIT (KDIM / GBK)       // 64
#define PITCH 40               // bf16 elems per smem row (32 data + 8 pad)
#define AHI_OFF 0
#define ALO_OFF 5120
#define BHI_OFF 10240
#define BLO_OFF 15360
#define STG_ELEMS 20480
#define GEMM_SMEM_BYTES (3 * STG_ELEMS * 2)   // 122880

__global__ __launch_bounds__(256, 1)
void gemm_kernel(const float* __restrict__ bias) {
    extern __shared__ __nv_bfloat16 sm[];
    const int tid = threadIdx.x;
    const int lane = tid & 31;
    const int wid = tid >> 5;
    const int wm = wid >> 1;               // 0..3
    const int wn = wid & 1;                // 0..1
    const int m0 = blockIdx.y * GBM;
    const int n0 = blockIdx.x * GBN;

    const int lr0 = tid >> 2, lc0 = (tid & 3) * 8;
    const int lr1 = (tid + 256) >> 2, lc1 = lc0;

    float acc[2][8][4];
#pragma unroll
    for (int mf = 0; mf < 2; ++mf)
#pragma unroll
        for (int nf = 0; nf < 8; ++nf)
#pragma unroll
            for (int q = 0; q < 4; ++q) acc[mf][nf][q] = 0.f;

    auto issue = [&](int kt) {
        const int st = kt % 3;
        const uint32_t sbase = smem_u32(sm + st * STG_ELEMS);
        const int k0 = kt * GBK;
        {
            const size_t ga0 = (size_t)(m0 + lr0) * KDIM + k0 + lc0;
            const size_t ga1 = (size_t)(m0 + lr1) * KDIM + k0 + lc1;
            const size_t gb0 = (size_t)(n0 + lr0) * KDIM + k0 + lc0;
            const size_t gb1 = (size_t)(n0 + lr1) * KDIM + k0 + lc1;
            const uint32_t da0 = sbase + 2 * (lr0 * PITCH + lc0);
            const uint32_t da1 = sbase + 2 * (lr1 * PITCH + lc1);
            cp_async16(da0 + 2 * AHI_OFF, g_xhi + ga0);
            cp_async16(da1 + 2 * AHI_OFF, g_xhi + ga1);
            cp_async16(da0 + 2 * ALO_OFF, g_xlo + ga0);
            cp_async16(da1 + 2 * ALO_OFF, g_xlo + ga1);
            cp_async16(da0 + 2 * BHI_OFF, g_whi + gb0);
            cp_async16(da1 + 2 * BHI_OFF, g_whi + gb1);
            cp_async16(da0 + 2 * BLO_OFF, g_wlo + gb0);
            cp_async16(da1 + 2 * BLO_OFF, g_wlo + gb1);
        }
        CP_COMMIT();
    };

    issue(0);
    issue(1);

    const int a_row = wm * 32 + (lane & 15);
    const int a_col = (lane >> 4) * 8;
    const int b_row = wn * 64 + ((lane >> 4) * 8) + (lane & 7);
    const int b_col = ((lane >> 3) & 1) * 8;

    for (int kt = 0; kt < NIT; ++kt) {
        CP_WAIT1();
        __syncthreads();
        const int st = kt % 3;
        const uint32_t sb = smem_u32(sm + st * STG_ELEMS);

#pragma unroll
        for (int ks = 0; ks < 2; ++ks) {
            uint32_t ahi[2][4], alo[2][4], bhi[8][2], blo[8][2];
#pragma unroll
            for (int mf = 0; mf < 2; ++mf) {
                uint32_t ad = sb + 2 * (AHI_OFF + (a_row + mf * 16) * PITCH + a_col + ks * 16);
                LDSM4(ahi[mf], ad);
                LDSM4(alo[mf], ad + 2 * (ALO_OFF - AHI_OFF));
            }
#pragma unroll
            for (int np = 0; np < 4; ++np) {
                uint32_t bd = sb + 2 * (BHI_OFF + (b_row + np * 16) * PITCH + b_col + ks * 16);
                uint32_t r[4];
                LDSM4(r, bd);
                bhi[2 * np][0] = r[0]; bhi[2 * np][1] = r[1];
                bhi[2 * np + 1][0] = r[2]; bhi[2 * np + 1][1] = r[3];
                LDSM4(r, bd + 2 * (BLO_OFF - BHI_OFF));
                blo[2 * np][0] = r[0]; blo[2 * np][1] = r[1];
                blo[2 * np + 1][0] = r[2]; blo[2 * np + 1][1] = r[3];
            }
#pragma unroll
            for (int mf = 0; mf < 2; ++mf)
#pragma unroll
                for (int nf = 0; nf < 8; ++nf) {
                    MMA16816(acc[mf][nf], ahi[mf], bhi[nf]);
                    MMA16816(acc[mf][nf], ahi[mf], blo[nf]);
                    MMA16816(acc[mf][nf], alo[mf], bhi[nf]);
                }
        }
        if (kt + 2 < NIT) issue(kt + 2);
    }

    const int tr = lane >> 2, tc = (lane & 3) * 2;
    const int mb = m0 + wm * 32, nb = n0 + wn * 64;
#pragma unroll
    for (int nf = 0; nf < 8; ++nf) {
        const int p = nb + nf * 8 + tc;
        const float b0 = __ldg(&bias[p]), b1 = __ldg(&bias[p + 1]);
#pragma unroll
        for (int mf = 0; mf < 2; ++mf) {
            const int m = mb + mf * 16 + tr;
            float2 v0 = make_float2(acc[mf][nf][0] + b0, acc[mf][nf][1] + b1);
            float2 v1 = make_float2(acc[mf][nf][2] + b0, acc[mf][nf][3] + b1);
            *(float2*)&g_h[(size_t)m * PDIM + p] = v0;
            *(float2*)&g_h[(size_t)(m + 8) * PDIM + p] = v1;
        }
    }
}

// ---------------- kernel 3: per-token gate epilogue (validated R3 code) ------
#define TT 32
#define SS_PITCH 68
#define HS_PITCH 260
#define LS_PITCH 65
#define EPI_SMEM_FLOATS (PDIM * SS_PITCH + TT * HS_PITCH + TT * LS_PITCH + TT)
#define EPI_SMEM_BYTES (EPI_SMEM_FLOATS * 4)

__global__ __launch_bounds__(256)
void epi_kernel(const float* __restrict__ mask,
                float* __restrict__ out_logits,
                float* __restrict__ out_topk) {
    extern __shared__ float smf[];
    float* Ss = smf;
    float* Hs = Ss + PDIM * SS_PITCH;
    float* Ls = Hs + TT * HS_PITCH;
    float* Rn = Ls + TT * LS_PITCH;

    const int tid = threadIdx.x;
    const int tok0 = blockIdx.x * TT;

    for (int i = tid; i < PDIM * 16; i += 256) {
        int p = i >> 4, c = (i & 15) * 4;
        float4 v = *(const float4*)&g_Ssc[p * EDIM + c];
        *(float4*)&Ss[p * SS_PITCH + c] = v;
    }
    for (int i = tid; i < TT * 64; i += 256) {
        int t = i >> 6, c = (i & 63) * 4;
        float4 v = *(const float4*)&g_h[(size_t)(tok0 + t) * PDIM + c];
        *(float4*)&Hs[t * HS_PITCH + c] = v;
    }
    __syncthreads();

    {
        int r = tid >> 3, sg = tid & 7;
        float ss = 0.f;
#pragma unroll
        for (int c = 0; c < 8; ++c) {
            float4 v = *(const float4*)&Hs[r * HS_PITCH + sg * 32 + c * 4];
            ss = fmaf(v.x, v.x, ss); ss = fmaf(v.y, v.y, ss);
            ss = fmaf(v.z, v.z, ss); ss = fmaf(v.w, v.w, ss);
        }
        ss += __shfl_xor_sync(0xffffffffu, ss, 1);
        ss += __shfl_xor_sync(0xffffffffu, ss, 2);
        ss += __shfl_xor_sync(0xffffffffu, ss, 4);
        if (sg == 0) Rn[r] = 1.0f / fmaxf(sqrtf(ss), 1e-12f);
    }
    __syncthreads();

    {
        const int e0 = (tid & 15) * 4;
        const int t0 = (tid >> 4) * 2;
        float acc[2][4];
#pragma unroll
        for (int a = 0; a < 2; ++a)
#pragma unroll
            for (int j = 0; j < 4; ++j) acc[a][j] = 0.f;

        for (int p = 0; p < PDIM; p += 4) {
            float4 h0 = *(const float4*)&Hs[t0 * HS_PITCH + p];
            float4 h1 = *(const float4*)&Hs[(t0 + 1) * HS_PITCH + p];
            float4 s0 = *(const float4*)&Ss[(p + 0) * SS_PITCH + e0];
            float4 s1 = *(const float4*)&Ss[(p + 1) * SS_PITCH + e0];
            float4 s2 = *(const float4*)&Ss[(p + 2) * SS_PITCH + e0];
            float4 s3 = *(const float4*)&Ss[(p + 3) * SS_PITCH + e0];
            float sj[4][4] = {{s0.x, s0.y, s0.z, s0.w},
                              {s1.x, s1.y, s1.z, s1.w},
                              {s2.x, s2.y, s2.z, s2.w},
                              {s3.x, s3.y, s3.z, s3.w}};
            float hh0[4] = {h0.x, h0.y, h0.z, h0.w};
            float hh1[4] = {h1.x, h1.y, h1.z, h1.w};
#pragma unroll
            for (int q = 0; q < 4; ++q)
#pragma unroll
                for (int j = 0; j < 4; ++j) {
                    acc[0][j] = fmaf(hh0[q], sj[q][j], acc[0][j]);
                    acc[1][j] = fmaf(hh1[q], sj[q][j], acc[1][j]);
                }
        }

        float4 mk = *(const float4*)&mask[e0];
        float mka[4] = {mk.x, mk.y, mk.z, mk.w};
#pragma unroll
        for (int a = 0; a < 2; ++a) {
            int t = t0 + a;
            float rv = Rn[t];
            float vv[4];
#pragma unroll
            for (int j = 0; j < 4; ++j) {
                float val = acc[a][j] * rv;
                if (mka[j] == 0.f) val = -1e9f;
                vv[j] = val;
                Ls[t * LS_PITCH + e0 + j] = val;
            }
            float4 v = make_float4(vv[0], vv[1], vv[2], vv[3]);
            *(float4*)&out_logits[(size_t)(tok0 + t) * EDIM + e0] = v;
        }
    }
    __syncthreads();

    if (tid < TT) {
        const int t = tid;
        float mx = -3.402823466e38f;
        for (int e = 0; e < EDIM; ++e) mx = fmaxf(mx, Ls[t * LS_PITCH + e]);
        float s[EDIM];
        float Z = 0.f;
        for (int e = 0; e < EDIM; ++e) {
            float ex = expf(Ls[t * LS_PITCH + e] - mx);
            s[e] = ex;
            Z += ex;
        }
        float invZ = 1.0f / Z;
        for (int e = 0; e < EDIM; ++e) s[e] = s[e] * invZ + 1e-14f;

        int cnt = 0;
        for (int j = 0; j < EDIM; ++j) {
            float vj = s[j];
            float G = 0.f;
            int eqb = 0;
            for (int i = 0; i < EDIM; ++i) {
                float vi = s[i];
                if (vi > vj) G += vi;
                if (vi == vj && i < j) eqb++;
            }
            if (G + (float)eqb * vj < 1.0f) cnt++;
        }
        int active = g_active;
        if (cnt > active) cnt = active;
        out_topk[tok0 + t] = (float)cnt;
    }
}

// ---------------------------------------------------------------------------
extern "C" void kernel_launch(void* const* d_in, const int* in_sizes, int n_in,
                              void* d_out, int out_size) {
    const float* x    = (const float*)d_in[0];
    const float* W    = (const float*)d_in[1];
    const float* b    = (const float*)d_in[2];
    const float* sim  = (const float*)d_in[3];
    const float* temp = (const float*)d_in[4];
    const float* mask = (const float*)d_in[5];
    float* out = (float*)d_out;

    cudaFuncSetAttribute(gemm_kernel, cudaFuncAttributeMaxDynamicSharedMemorySize,
                         GEMM_SMEM_BYTES);
    cudaFuncSetAttribute(epi_kernel, cudaFuncAttributeMaxDynamicSharedMemorySize,
                         EPI_SMEM_BYTES);

    prep_kernel<<<1, 256>>>(sim, temp, mask);
    split_w_kernel<<<(PDIM * KDIM) / (256 * 8), 256>>>(W);
    split_x_kernel<<<(NTOK * KDIM) / (256 * 8), 256>>>(x);
    gemm_kernel<<<dim3(PDIM / GBN, NTOK / GBM), 256, GEMM_SMEM_BYTES>>>(b);
    epi_kernel<<<NTOK / TT, 256, EPI_SMEM_BYTES>>>(mask, out, out + (size_t)NTOK * EDIM);
}